// round 1
// baseline (speedup 1.0000x reference)
#include <cuda_runtime.h>
#include <cstdint>

// SkeletonLinear: out = x @ (W .* M)^T + b
// x: [32768, 768] f32, W/M: [768, 768] f32, b: [768] f32, out: [32768, 768] f32
// Mask is block-sparse: dst node d reads only src nodes {d-1, d} (24 nodes, 32 ch each).

#define NODES   24
#define CH      32
#define DIM     768          // 24 * 32
#define BATCH   32768
#define ROWS    128          // batch rows per CTA
#define THREADS 256

__device__ __forceinline__ void ffma2(unsigned long long& acc,
                                      unsigned long long a,
                                      unsigned long long b) {
    // packed fp32x2 FMA (Blackwell); ptxas will not auto-generate this
    asm("fma.rn.f32x2 %0, %1, %2, %0;" : "+l"(acc) : "l"(a), "l"(b));
}

__global__ void __launch_bounds__(THREADS)
skeleton_linear_kernel(const float* __restrict__ x,
                       const float* __restrict__ w,
                       const float* __restrict__ bias,
                       const float* __restrict__ mask,
                       float* __restrict__ out) {
    // CTA: batch tile blockIdx.x (ROWS rows), node d = blockIdx.y
    const int d    = blockIdx.y;
    const int row0 = blockIdx.x * ROWS;
    const int tid  = threadIdx.x;

    // 64-col input window [col0, col0+64). For d==0 it starts at 0; the mask
    // multiply zeroes the half that belongs to a non-edge source.
    const int col0 = (d == 0) ? 0 : (d - 1) * CH;

    // xs: [ROWS][32 k2-pairs] as float2 (packed adjacent k)  -> 32 KB
    // ws: [32 k2][32 o]       as float2 (k2-major, transposed) -> 8 KB
    __shared__ float2 xs[ROWS * 32];
    __shared__ float2 ws[32 * 32];
    __shared__ float  bs[CH];

    // ---- stage x tile: 128 rows x 64 cols, coalesced float4 loads ----
    {
        float4* xs4 = reinterpret_cast<float4*>(xs);
        #pragma unroll
        for (int it = 0; it < (ROWS * 16) / THREADS; ++it) {
            int idx = tid + it * THREADS;          // 0..2047
            int r   = idx >> 4;                    // row in tile
            int c4  = idx & 15;                    // which float4 of 16
            const float4* src = reinterpret_cast<const float4*>(
                x + (size_t)(row0 + r) * DIM + col0);
            xs4[r * 16 + c4] = src[c4];
        }
    }

    // ---- stage weights (masked) transposed to k2-major ----
    {
        #pragma unroll
        for (int it = 0; it < (CH * 16) / THREADS; ++it) {
            int idx = tid + it * THREADS;          // 0..511
            int o   = idx & 31;                    // output channel within node
            int c4  = idx >> 5;                    // float4 index along k (0..15)
            size_t g = (size_t)(d * CH + o) * DIM + col0 + c4 * 4;
            float4 wv = *reinterpret_cast<const float4*>(w + g);
            float4 mv = *reinterpret_cast<const float4*>(mask + g);
            int k2 = c4 * 2;
            ws[(k2)     * 32 + o] = make_float2(wv.x * mv.x, wv.y * mv.y);
            ws[(k2 + 1) * 32 + o] = make_float2(wv.z * mv.z, wv.w * mv.w);
        }
        if (tid < CH) bs[tid] = bias[d * CH + tid];
    }

    __syncthreads();

    // ---- compute: 4 rows x 4 outputs per thread, packed-k2 FMAs ----
    const int og = tid & 7;        // 8 output groups * 4 = 32 outputs
    const int rg = tid >> 3;       // 32 row groups   * 4 = 128 rows
    const int o0 = og * 4;
    const int r0 = rg * 4;

    const unsigned long long* xs2 = reinterpret_cast<const unsigned long long*>(xs);
    const unsigned long long* ws2 = reinterpret_cast<const unsigned long long*>(ws);

    unsigned long long acc[4][4];
    #pragma unroll
    for (int i = 0; i < 4; ++i)
        #pragma unroll
        for (int j = 0; j < 4; ++j) acc[i][j] = 0ull;

    #pragma unroll 4
    for (int k2 = 0; k2 < 32; ++k2) {
        unsigned long long xv[4], wv[4];
        #pragma unroll
        for (int i = 0; i < 4; ++i) xv[i] = xs2[(r0 + i) * 32 + k2];
        #pragma unroll
        for (int j = 0; j < 4; ++j) wv[j] = ws2[k2 * 32 + o0 + j];
        #pragma unroll
        for (int i = 0; i < 4; ++i)
            #pragma unroll
            for (int j = 0; j < 4; ++j)
                ffma2(acc[i][j], xv[i], wv[j]);
    }

    // ---- epilogue: reduce packed halves, add bias, vectorized store ----
    #pragma unroll
    for (int i = 0; i < 4; ++i) {
        float4 res;
        float* rp = reinterpret_cast<float*>(&res);
        #pragma unroll
        for (int j = 0; j < 4; ++j) {
            float2 a = *reinterpret_cast<float2*>(&acc[i][j]);
            rp[j] = a.x + a.y + bs[o0 + j];
        }
        size_t g = (size_t)(row0 + r0 + i) * DIM + d * CH + o0;
        *reinterpret_cast<float4*>(out + g) = res;
    }
}

extern "C" void kernel_launch(void* const* d_in, const int* in_sizes, int n_in,
                              void* d_out, int out_size) {
    const float* x    = (const float*)d_in[0];
    const float* w    = (const float*)d_in[1];
    const float* b    = (const float*)d_in[2];
    const float* m    = (const float*)d_in[3];
    float* out = (float*)d_out;

    dim3 grid(BATCH / ROWS, NODES);  // (256, 24)
    skeleton_linear_kernel<<<grid, THREADS>>>(x, w, b, m, out);
}

// round 2
// speedup vs baseline: 1.2062x; 1.2062x over previous
#include <cuda_runtime.h>
#include <cstdint>

// SkeletonLinear: out = x @ (W .* M)^T + b
// x: [32768, 768] f32, W/M: [768, 768] f32, b: [768] f32, out: [32768, 768] f32
// Block-sparse mask: dst node d reads only src nodes {d-1, d} (24 nodes, 32 ch).
//
// Design (R2): CTA = 128 threads, 128 rows, one node. Each thread owns 2 full
// rows x 16 outputs (acc = 32 x f32x2). x staged transposed [k2][row] (pad 130)
// so the per-k2 x read is one LDS.128 covering both rows; weights (masked,
// k2-major) read as warp-uniform broadcast LDS.128. 12 smem wavefronts per
// 32 packed FMAs -> fma-pipe-bound instead of crossbar-bound.

#define NODES   24
#define CH      32
#define DIM     768
#define BATCH   32768
#define ROWS    128
#define THREADS 128
#define XSTRIDE 130   // float2 units per k2 row (128 + pad 2, keeps 16B align)

__device__ __forceinline__ void ffma2(unsigned long long& acc,
                                      unsigned long long a,
                                      unsigned long long b) {
    asm("fma.rn.f32x2 %0, %1, %2, %0;" : "+l"(acc) : "l"(a), "l"(b));
}

__global__ void __launch_bounds__(THREADS)
skeleton_linear_kernel(const float* __restrict__ x,
                       const float* __restrict__ w,
                       const float* __restrict__ bias,
                       const float* __restrict__ mask,
                       float* __restrict__ out) {
    const int d    = blockIdx.y;
    const int row0 = blockIdx.x * ROWS;
    const int tid  = threadIdx.x;

    // 64-col input window; mask multiply zeroes the non-edge half for d==0.
    const int col0 = (d == 0) ? 0 : (d - 1) * CH;

    __shared__ __align__(16) float2 xs[32 * XSTRIDE];  // [k2][row] transposed, 33.3 KB
    __shared__ __align__(16) float2 ws[32 * 32];       // [k2][o] masked weights, 8 KB
    __shared__ float bs[CH];

    // ---- stage x transposed: gmem coalesced float4, smem [k2][row] ----
    #pragma unroll
    for (int it = 0; it < (ROWS * 16) / THREADS; ++it) {
        int idx = tid + it * THREADS;          // 0..2047
        int r   = idx >> 4;
        int c4  = idx & 15;                    // float4 index along k (0..15)
        float4 v = *reinterpret_cast<const float4*>(
            x + (size_t)(row0 + r) * DIM + col0 + c4 * 4);
        int k2 = c4 * 2;
        xs[(k2)     * XSTRIDE + r] = make_float2(v.x, v.y);
        xs[(k2 + 1) * XSTRIDE + r] = make_float2(v.z, v.w);
    }

    // ---- stage weights (masked), k2-major ----
    #pragma unroll
    for (int it = 0; it < (CH * 16) / THREADS; ++it) {
        int idx = tid + it * THREADS;          // 0..511
        int o   = idx & 31;
        int c4  = idx >> 5;
        size_t g = (size_t)(d * CH + o) * DIM + col0 + c4 * 4;
        float4 wv = *reinterpret_cast<const float4*>(w + g);
        float4 mv = *reinterpret_cast<const float4*>(mask + g);
        int k2 = c4 * 2;
        ws[(k2)     * 32 + o] = make_float2(wv.x * mv.x, wv.y * mv.y);
        ws[(k2 + 1) * 32 + o] = make_float2(wv.z * mv.z, wv.w * mv.w);
    }
    if (tid < CH) bs[tid] = bias[d * CH + tid];

    __syncthreads();

    // ---- compute: 2 rows x 16 outputs per thread ----
    const int half = tid >> 6;        // warps 0-1: o 0..15, warps 2-3: o 16..31
    const int o0   = half * 16;
    const int tt   = tid & 63;        // 64 threads per half -> 128 rows (2 each)
    const int r0   = tt * 2;

    unsigned long long acc[2][16];
    #pragma unroll
    for (int i = 0; i < 2; ++i)
        #pragma unroll
        for (int j = 0; j < 16; ++j) acc[i][j] = 0ull;

    #pragma unroll 4
    for (int k2 = 0; k2 < 32; ++k2) {
        // x for both rows: one LDS.128
        ulonglong2 xq = *reinterpret_cast<const ulonglong2*>(&xs[k2 * XSTRIDE + r0]);
        unsigned long long xv[2] = {xq.x, xq.y};
        // weights: 8 warp-uniform broadcast LDS.128 (16 outputs)
        ulonglong2 wq[8];
        #pragma unroll
        for (int j = 0; j < 8; ++j)
            wq[j] = *reinterpret_cast<const ulonglong2*>(&ws[k2 * 32 + o0 + 2 * j]);
        #pragma unroll
        for (int i = 0; i < 2; ++i)
            #pragma unroll
            for (int j = 0; j < 8; ++j) {
                ffma2(acc[i][2 * j],     xv[i], wq[j].x);
                ffma2(acc[i][2 * j + 1], xv[i], wq[j].y);
            }
    }

    // ---- epilogue: reduce packed halves, add bias, float4 stores ----
    #pragma unroll
    for (int i = 0; i < 2; ++i) {
        size_t rowg = (size_t)(row0 + r0 + i) * DIM + d * CH + o0;
        #pragma unroll
        for (int j4 = 0; j4 < 4; ++j4) {
            float4 res;
            float* rp = reinterpret_cast<float*>(&res);
            #pragma unroll
            for (int c = 0; c < 4; ++c) {
                float2 a = *reinterpret_cast<float2*>(&acc[i][4 * j4 + c]);
                rp[c] = a.x + a.y + bs[o0 + 4 * j4 + c];
            }
            *reinterpret_cast<float4*>(out + rowg + 4 * j4) = res;
        }
    }
}

extern "C" void kernel_launch(void* const* d_in, const int* in_sizes, int n_in,
                              void* d_out, int out_size) {
    const float* x    = (const float*)d_in[0];
    const float* w    = (const float*)d_in[1];
    const float* b    = (const float*)d_in[2];
    const float* m    = (const float*)d_in[3];
    float* out = (float*)d_out;

    dim3 grid(BATCH / ROWS, NODES);  // (256, 24)
    skeleton_linear_kernel<<<grid, THREADS>>>(x, w, b, m, out);
}

// round 3
// speedup vs baseline: 1.3238x; 1.0975x over previous
#include <cuda_runtime.h>
#include <cstdint>

// SkeletonLinear: out = x @ (W .* M)^T + b
// x: [32768, 768] f32, W/M: [768, 768] f32, b: [768], out: [32768, 768] f32
// Block-sparse mask: dst node d reads src nodes {d-1, d} only (24 nodes x 32ch).
//
// R3: CTA = 128 thr / 128 rows / 1 node. Thread tile = 8 rows x 4 outputs,
// lane = (r_local = lane>>3, o4 = lane&7). All compute LDS are conflict-free /
// broadcast (6 wavefronts per warp-k2 for 32 FFMA2), and epilogue stores are
// line-coalesced (4 x 128B lines per warp store instr). Packed f32x2 FMAs.

#define NODES   24
#define CH      32
#define DIM     768
#define BATCH   32768
#define ROWS    128
#define THREADS 128
#define XSTRIDE 130   // float2 units per k2 row (128 + pad), keeps 16B align

__device__ __forceinline__ void ffma2(unsigned long long& acc,
                                      unsigned long long a,
                                      unsigned long long b) {
    asm("fma.rn.f32x2 %0, %1, %2, %0;" : "+l"(acc) : "l"(a), "l"(b));
}

__global__ void __launch_bounds__(THREADS)
skeleton_linear_kernel(const float* __restrict__ x,
                       const float* __restrict__ w,
                       const float* __restrict__ bias,
                       const float* __restrict__ mask,
                       float* __restrict__ out) {
    const int d    = blockIdx.y;
    const int row0 = blockIdx.x * ROWS;
    const int tid  = threadIdx.x;

    // 64-col input window; mask multiply zeroes the non-edge half for d==0.
    const int col0 = (d == 0) ? 0 : (d - 1) * CH;

    __shared__ __align__(16) float2 xs[32 * XSTRIDE];  // [k2][row] transposed
    __shared__ __align__(16) float2 ws[32 * 32];       // [k2][o] masked weights
    __shared__ float bs[CH];

    // ---- stage x transposed: gmem coalesced float4, smem [k2][row] ----
    #pragma unroll
    for (int it = 0; it < (ROWS * 16) / THREADS; ++it) {
        int idx = tid + it * THREADS;          // 0..2047
        int r   = idx >> 4;
        int c4  = idx & 15;                    // float4 index along k (0..15)
        float4 v = *reinterpret_cast<const float4*>(
            x + (size_t)(row0 + r) * DIM + col0 + c4 * 4);
        int k2 = c4 * 2;
        xs[(k2)     * XSTRIDE + r] = make_float2(v.x, v.y);
        xs[(k2 + 1) * XSTRIDE + r] = make_float2(v.z, v.w);
    }

    // ---- stage weights (masked), k2-major ----
    #pragma unroll
    for (int it = 0; it < (CH * 16) / THREADS; ++it) {
        int idx = tid + it * THREADS;          // 0..511
        int o   = idx & 31;
        int c4  = idx >> 5;
        size_t g = (size_t)(d * CH + o) * DIM + col0 + c4 * 4;
        float4 wv = *reinterpret_cast<const float4*>(w + g);
        float4 mv = *reinterpret_cast<const float4*>(mask + g);
        int k2 = c4 * 2;
        ws[(k2)     * 32 + o] = make_float2(wv.x * mv.x, wv.y * mv.y);
        ws[(k2 + 1) * 32 + o] = make_float2(wv.z * mv.z, wv.w * mv.w);
    }
    if (tid < CH) bs[tid] = bias[d * CH + tid];

    __syncthreads();

    // ---- compute: 8 rows x 4 outputs per thread ----
    const int lane    = tid & 31;
    const int warp    = tid >> 5;
    const int r_local = lane >> 3;           // 0..3
    const int o0      = (lane & 7) * 4;      // 4-output group
    const int base    = warp * 32 + r_local * 2;   // rows: base + 8*jj + i

    unsigned long long acc[4][2][4];         // [jj][i][o], 32 x f32x2
    #pragma unroll
    for (int jj = 0; jj < 4; ++jj)
        #pragma unroll
        for (int i = 0; i < 2; ++i)
            #pragma unroll
            for (int o = 0; o < 4; ++o) acc[jj][i][o] = 0ull;

    #pragma unroll 4
    for (int k2 = 0; k2 < 32; ++k2) {
        // weights for 4 outputs: 2 x LDS.128, 128B-contiguous across warp
        ulonglong2 wq0 = *reinterpret_cast<const ulonglong2*>(&ws[k2 * 32 + o0]);
        ulonglong2 wq1 = *reinterpret_cast<const ulonglong2*>(&ws[k2 * 32 + o0 + 2]);
        unsigned long long wv[4] = {wq0.x, wq0.y, wq1.x, wq1.y};

        #pragma unroll
        for (int jj = 0; jj < 4; ++jj) {
            // x for rows base+8jj, base+8jj+1: one LDS.128, 64B-contiguous/warp
            ulonglong2 xq = *reinterpret_cast<const ulonglong2*>(
                &xs[k2 * XSTRIDE + base + 8 * jj]);
            unsigned long long xv[2] = {xq.x, xq.y};
            #pragma unroll
            for (int i = 0; i < 2; ++i)
                #pragma unroll
                for (int o = 0; o < 4; ++o)
                    ffma2(acc[jj][i][o], xv[i], wv[o]);
        }
    }

    // ---- epilogue: reduce halves, add bias, line-coalesced float4 stores ----
    #pragma unroll
    for (int jj = 0; jj < 4; ++jj)
        #pragma unroll
        for (int i = 0; i < 2; ++i) {
            float4 res;
            float* rp = reinterpret_cast<float*>(&res);
            #pragma unroll
            for (int o = 0; o < 4; ++o) {
                float2 a = *reinterpret_cast<float2*>(&acc[jj][i][o]);
                rp[o] = a.x + a.y + bs[o0 + o];
            }
            size_t g = (size_t)(row0 + base + 8 * jj + i) * DIM + d * CH + o0;
            *reinterpret_cast<float4*>(out + g) = res;
        }
}

extern "C" void kernel_launch(void* const* d_in, const int* in_sizes, int n_in,
                              void* d_out, int out_size) {
    const float* x    = (const float*)d_in[0];
    const float* w    = (const float*)d_in[1];
    const float* b    = (const float*)d_in[2];
    const float* m    = (const float*)d_in[3];
    float* out = (float*)d_out;

    dim3 grid(BATCH / ROWS, NODES);  // (256, 24)
    skeleton_linear_kernel<<<grid, THREADS>>>(x, w, b, m, out);
}